// round 4
// baseline (speedup 1.0000x reference)
#include <cuda_runtime.h>
#include <cuda_fp16.h>

#define BATCH   8192
#define CLASSES 10000
#define C4      2500            // float4 per row
#define ROWS    4               // rows per block (80 KB smem -> 2 CTAs/SM)
#define THREADS 512
#define NREP    16              // replica accumulator arrays (atomic spreading)
#define NBLOCKS (BATCH / ROWS)  // 2048
#define SMEM_BYTES (ROWS * CLASSES * 2)   // 80000 B fp16 exp cache

__device__ float g_part[NREP][CLASSES];
__device__ float g_counts[CLASSES];

// ---------------------------------------------------------------- zero accumulators + out
__global__ void k_zero(float* __restrict__ out) {
    int i = blockIdx.x * blockDim.x + threadIdx.x;
    if (i < CLASSES) {
        g_counts[i] = 0.0f;
        #pragma unroll
        for (int r = 0; r < NREP; r++) g_part[r][i] = 0.0f;
    }
    if (i == 0) out[0] = 0.0f;
}

// ---------------------------------------------------------------- fused single-read kernel
// Block b owns rows [ROWS*b, ROWS*(b+1)). Phase A: read rows once (float4,
// coalesced), fp32 exp, cache fp16 in SMEM, fp32 row sums. Phase B: sweep
// classes from SMEM, one atomicAdd per class per block into a replica array.
// Blocks 0..7 additionally compute the label histogram (1024 targets each).
__global__ __launch_bounds__(THREADS, 2) void k_main(const float* __restrict__ x,
                                                     const int* __restrict__ tgt) {
    extern __shared__ __half sm_exp[];      // [ROWS][CLASSES]
    __shared__ float wsum[16];
    __shared__ float inv[ROWS];

    const int tid     = threadIdx.x;
    const int r       = tid >> 7;           // 0..3  (128 threads per row)
    const int lane128 = tid & 127;
    const size_t row  = (size_t)blockIdx.x * ROWS + r;

    // ---- histogram side-job (8 blocks x 1024 targets), dtype-robust:
    // detect int64-LE (odd int32 words zero for values < 2^32) vs int32.
    if (blockIdx.x < 8) {
        bool is64 = true;
        #pragma unroll
        for (int j = 1; j < 16; j += 2) is64 = is64 && (tgt[j] == 0);
        int base = blockIdx.x * 1024;
        #pragma unroll
        for (int k = 0; k < 1024 / THREADS; k++) {
            int i = base + k * THREADS + tid;
            int t = is64 ? tgt[2 * i] : tgt[i];
            if (t >= 0 && t < CLASSES) atomicAdd(&g_counts[t], 1.0f);
        }
    }

    const float4* __restrict__ rowp =
        reinterpret_cast<const float4*>(x + row * CLASSES);
    uint2* smrow8 = reinterpret_cast<uint2*>(sm_exp + r * CLASSES);  // STS.64

    float s = 0.0f;
    #pragma unroll 4
    for (int i = lane128; i < C4; i += 128) {
        float4 v = rowp[i];
        float e0 = __expf(v.x), e1 = __expf(v.y);
        float e2 = __expf(v.z), e3 = __expf(v.w);
        s += (e0 + e1) + (e2 + e3);
        __half2 h01 = __floats2half2_rn(e0, e1);
        __half2 h23 = __floats2half2_rn(e2, e3);
        smrow8[i] = make_uint2(*reinterpret_cast<unsigned*>(&h01),
                               *reinterpret_cast<unsigned*>(&h23));
    }

    // reduce 128 threads per row: warp shfl -> 4 warp sums -> combine
    #pragma unroll
    for (int o = 16; o; o >>= 1) s += __shfl_down_sync(0xffffffffu, s, o);
    if ((tid & 31) == 0) wsum[tid >> 5] = s;
    __syncthreads();
    if (tid < ROWS) {
        float t = wsum[4 * tid] + wsum[4 * tid + 1] +
                  wsum[4 * tid + 2] + wsum[4 * tid + 3];
        inv[tid] = 1.0f / t;
    }
    __syncthreads();

    // Phase B: per-class accumulation from SMEM (half2 = 2 classes at a time)
    float iv[ROWS];
    #pragma unroll
    for (int rr = 0; rr < ROWS; rr++) iv[rr] = inv[rr];

    float* __restrict__ dst = g_part[blockIdx.x & (NREP - 1)];
    const __half2* smh2 = reinterpret_cast<const __half2*>(sm_exp);

    for (int j = tid; j < CLASSES / 2; j += THREADS) {
        float a0 = 0.0f, a1 = 0.0f;
        #pragma unroll
        for (int rr = 0; rr < ROWS; rr++) {
            float2 f = __half22float2(smh2[rr * (CLASSES / 2) + j]);
            a0 += f.x * iv[rr];
            a1 += f.y * iv[rr];
        }
        atomicAdd(&dst[2 * j],     a0);
        atomicAdd(&dst[2 * j + 1], a1);
    }
}

// ---------------------------------------------------------------- final L1 reduce
__global__ __launch_bounds__(256) void k_final(float* __restrict__ out) {
    const float invB = 1.0f / (float)BATCH;
    float s = 0.0f;
    for (int c = blockIdx.x * 256 + threadIdx.x; c < CLASSES; c += gridDim.x * 256) {
        float v = 0.0f;
        #pragma unroll
        for (int r = 0; r < NREP; r++) v += g_part[r][c];
        s += fabsf((v - g_counts[c]) * invB);
    }
    __shared__ float sm[8];
    #pragma unroll
    for (int o = 16; o; o >>= 1) s += __shfl_down_sync(0xffffffffu, s, o);
    if ((threadIdx.x & 31) == 0) sm[threadIdx.x >> 5] = s;
    __syncthreads();
    if (threadIdx.x < 8) {
        float t = sm[threadIdx.x];
        #pragma unroll
        for (int o = 4; o; o >>= 1) t += __shfl_down_sync(0xffu, t, o);
        if (threadIdx.x == 0) atomicAdd(out, t / (float)CLASSES);
    }
}

// ---------------------------------------------------------------- launch
extern "C" void kernel_launch(void* const* d_in, const int* in_sizes, int n_in,
                              void* d_out, int out_size) {
    const float* x   = (const float*)d_in[0];   // [8192, 10000] fp32
    const int*   tgt = (const int*)d_in[1];     // [8192] int32 or int64 (detected)
    float*       out = (float*)d_out;

    cudaFuncSetAttribute(k_main, cudaFuncAttributeMaxDynamicSharedMemorySize,
                         SMEM_BYTES);

    k_zero<<<(CLASSES + 255) / 256, 256>>>(out);
    k_main<<<NBLOCKS, THREADS, SMEM_BYTES>>>(x, tgt);   // 2048 blocks, 2/SM
    k_final<<<40, 256>>>(out);
}